// round 2
// baseline (speedup 1.0000x reference)
#include <cuda_runtime.h>

// Problem dims (fixed by the dataset)
#define B_   32
#define T_   512
#define IN_  512
#define H_   1024
#define OUT_ 512

// ---------------------------------------------------------------------------
// Device scratch (allocation-free rule: __device__ globals)
// ---------------------------------------------------------------------------
__device__ float g_xp[(size_t)B_ * T_ * H_];   // x@Wx + bx + bh, [B][T][H], 64MB
__device__ float g_hs[(size_t)B_ * T_ * H_];   // hidden states   [B][T][H], 64MB
__device__ unsigned g_bar = 0;                 // grid barrier counter

// ---------------------------------------------------------------------------
// f32x2 packed math helpers (Blackwell FFMA2 path; reg-reg FFMA is rt=2,
// packed f32x2 doubles FMA throughput per issue slot)
// ---------------------------------------------------------------------------
__device__ __forceinline__ unsigned long long ffma2(unsigned long long a,
                                                    unsigned long long b,
                                                    unsigned long long c) {
    unsigned long long d;
    asm("fma.rn.f32x2 %0, %1, %2, %3;" : "=l"(d) : "l"(a), "l"(b), "l"(c));
    return d;
}
__device__ __forceinline__ unsigned long long splat2(float x) {
    unsigned long long d;
    asm("mov.b64 %0, {%1, %2};" : "=l"(d) : "f"(x), "f"(x));
    return d;
}
__device__ __forceinline__ float2 unpack2(unsigned long long d) {
    float2 r;
    asm("mov.b64 {%0, %1}, %2;" : "=f"(r.x), "=f"(r.y) : "l"(d));
    return r;
}

// ---------------------------------------------------------------------------
// SGEMM with bias epilogue: C[M,N] = A[M,K] @ Bm[K,N] + b1 (+ b2)
// 128x128 tile, BK=16, 256 threads, 8x8 per-thread tile via f32x2.
// All shapes here are multiples of the tile sizes -> no bounds checks.
// Also resets the grid-barrier counter (runs before the scan kernel).
// ---------------------------------------------------------------------------
__global__ __launch_bounds__(256, 2) void sgemm_bias_kernel(
    const float* __restrict__ A, const float* __restrict__ Bm,
    const float* __restrict__ b1p, const float* __restrict__ b2p,
    float* __restrict__ C, int M, int N, int K)
{
    if (blockIdx.x == 0 && blockIdx.y == 0 && threadIdx.x == 0) g_bar = 0u;

    __shared__ __align__(16) float As[16][128];   // transposed: As[k][m]
    __shared__ __align__(16) float Bs[16][128];   // Bs[k][n]

    const int tid  = threadIdx.x;
    const int row0 = blockIdx.y * 128;
    const int col0 = blockIdx.x * 128;
    const int tx   = tid & 15;        // 0..15 -> n
    const int ty   = tid >> 4;        // 0..15 -> m

    const int aRow = tid >> 2;        // 0..63
    const int aK4  = (tid & 3) * 4;   // 0,4,8,12
    const int bRow = tid >> 5;        // 0..7
    const int bCol = (tid & 31) * 4;  // 0..124

    unsigned long long acc[8][4];
#pragma unroll
    for (int i = 0; i < 8; i++)
#pragma unroll
        for (int j = 0; j < 4; j++) acc[i][j] = 0ull;

    for (int k0 = 0; k0 < K; k0 += 16) {
        float4 av0 = *(const float4*)(A + (size_t)(row0 + aRow)      * K + k0 + aK4);
        float4 av1 = *(const float4*)(A + (size_t)(row0 + aRow + 64) * K + k0 + aK4);
        float4 bv0 = *(const float4*)(Bm + (size_t)(k0 + bRow)     * N + col0 + bCol);
        float4 bv1 = *(const float4*)(Bm + (size_t)(k0 + bRow + 8) * N + col0 + bCol);

        __syncthreads();   // previous iteration done reading smem
        As[aK4 + 0][aRow] = av0.x;  As[aK4 + 1][aRow] = av0.y;
        As[aK4 + 2][aRow] = av0.z;  As[aK4 + 3][aRow] = av0.w;
        As[aK4 + 0][aRow + 64] = av1.x;  As[aK4 + 1][aRow + 64] = av1.y;
        As[aK4 + 2][aRow + 64] = av1.z;  As[aK4 + 3][aRow + 64] = av1.w;
        *(float4*)&Bs[bRow][bCol]     = bv0;
        *(float4*)&Bs[bRow + 8][bCol] = bv1;
        __syncthreads();

#pragma unroll
        for (int kk = 0; kk < 16; kk++) {
            float4 a0 = *(const float4*)&As[kk][ty * 8];
            float4 a1 = *(const float4*)&As[kk][ty * 8 + 4];
            const unsigned long long* bp =
                (const unsigned long long*)&Bs[kk][tx * 8];
            unsigned long long bq0 = bp[0], bq1 = bp[1], bq2 = bp[2], bq3 = bp[3];
            float av[8] = {a0.x, a0.y, a0.z, a0.w, a1.x, a1.y, a1.z, a1.w};
#pragma unroll
            for (int i = 0; i < 8; i++) {
                unsigned long long a2 = splat2(av[i]);
                acc[i][0] = ffma2(a2, bq0, acc[i][0]);
                acc[i][1] = ffma2(a2, bq1, acc[i][1]);
                acc[i][2] = ffma2(a2, bq2, acc[i][2]);
                acc[i][3] = ffma2(a2, bq3, acc[i][3]);
            }
        }
    }

    // Epilogue: bias add + store
    const int crow = row0 + ty * 8;
    const int ccol = col0 + tx * 8;
    float bsum[8];
#pragma unroll
    for (int j = 0; j < 8; j++) {
        float bv = b1p[ccol + j];
        if (b2p) bv += b2p[ccol + j];
        bsum[j] = bv;
    }
#pragma unroll
    for (int i = 0; i < 8; i++) {
        float o[8];
#pragma unroll
        for (int j4 = 0; j4 < 4; j4++) {
            float2 v = unpack2(acc[i][j4]);
            o[2 * j4]     = v.x + bsum[2 * j4];
            o[2 * j4 + 1] = v.y + bsum[2 * j4 + 1];
        }
        float4* cp = (float4*)(C + (size_t)(crow + i) * N + ccol);
        cp[0] = make_float4(o[0], o[1], o[2], o[3]);
        cp[1] = make_float4(o[4], o[5], o[6], o[7]);
    }
}

// ---------------------------------------------------------------------------
// Persistent RNN scan kernel.
// grid = 128 blocks (<= 148 SMs, co-resident; software grid barrier per step)
// block = 128 threads; thread (b, jp): b = tid>>2 in [0,32), jp = tid&3.
// Each block owns j-columns [bx*8, bx*8+8) and caches its Wh slab (1024x8,
// 32KB) in static smem for the whole scan. Each thread produces a packed
// f32x2 pair of outputs per step.
// ---------------------------------------------------------------------------
#define STEP4(hv, off)                                  \
    acc = ffma2(splat2(hv.x), wp[(off) + 0],  acc);     \
    acc = ffma2(splat2(hv.y), wp[(off) + 4],  acc);     \
    acc = ffma2(splat2(hv.z), wp[(off) + 8],  acc);     \
    acc = ffma2(splat2(hv.w), wp[(off) + 12], acc);

__global__ __launch_bounds__(128, 1) void rnn_scan_kernel(
    const float* __restrict__ h0,   // [B][H] initial hidden
    const float* __restrict__ Wh,   // [H][H]
    float* __restrict__ next_h)     // [B][H] (tail of d_out)
{
    __shared__ __align__(16) float whs[H_ * 8];   // [k][j], j local 0..7

    const int tid   = threadIdx.x;
    const int b     = tid >> 2;
    const int jp    = tid & 3;
    const int jbase = blockIdx.x * 8;

    // Load this block's Wh slab once (step-invariant).
    for (int idx = tid; idx < H_ * 8; idx += 128) {
        int k = idx >> 3, j = idx & 7;
        whs[idx] = Wh[(size_t)k * H_ + jbase + j];
    }
    __syncthreads();
    const unsigned long long* whs2 = (const unsigned long long*)whs; // [k*4+jp]

    const int brow   = b * (T_ * H_);
    unsigned  target = gridDim.x;

    for (int t = 0; t < T_; t++) {
        const float* hprev = (t == 0) ? (h0 + b * H_)
                                      : (g_hs + brow + (t - 1) * H_);
        unsigned long long acc =
            *(const unsigned long long*)(g_xp + brow + t * H_ + jbase + 2 * jp);

#pragma unroll 4
        for (int k = 0; k < H_; k += 16) {
            float4 ha = *(const float4*)(hprev + k);
            float4 hb = *(const float4*)(hprev + k + 4);
            float4 hc = *(const float4*)(hprev + k + 8);
            float4 hd = *(const float4*)(hprev + k + 12);
            const unsigned long long* wp = whs2 + k * 4 + jp;
            STEP4(ha, 0)
            STEP4(hb, 16)
            STEP4(hc, 32)
            STEP4(hd, 48)
        }

        float2 v = unpack2(acc);
        v.x = tanhf(v.x);
        v.y = tanhf(v.y);
        *(float2*)(g_hs + brow + t * H_ + jbase + 2 * jp) = v;
        if (t == T_ - 1)
            *(float2*)(next_h + b * H_ + jbase + 2 * jp) = v;

        // ---- grid barrier ----
        __threadfence();
        __syncthreads();
        if (tid == 0) {
            unsigned arrived = atomicAdd(&g_bar, 1u) + 1u;
            if (arrived < target) {
                while (*(volatile unsigned*)&g_bar < target) { }
            }
        }
        __syncthreads();
        target += gridDim.x;
    }
}

// ---------------------------------------------------------------------------
// kernel_launch: 4 launches, all graph-capturable, default stream.
// Inputs: 0:x 1:h 2:Wx 3:bx 4:Wh 5:bh 6:W1 7:b1 8:W2 9:b2
// Output: [td0 (B*T*OUT) | td1 (B*T*OUT) | next_h (B*H)]
// ---------------------------------------------------------------------------
extern "C" void kernel_launch(void* const* d_in, const int* in_sizes, int n_in,
                              void* d_out, int out_size)
{
    (void)in_sizes; (void)n_in; (void)out_size;
    const float* x  = (const float*)d_in[0];
    const float* h  = (const float*)d_in[1];
    const float* Wx = (const float*)d_in[2];
    const float* bx = (const float*)d_in[3];
    const float* Wh = (const float*)d_in[4];
    const float* bh = (const float*)d_in[5];
    const float* W1 = (const float*)d_in[6];
    const float* b1 = (const float*)d_in[7];
    const float* W2 = (const float*)d_in[8];
    const float* b2 = (const float*)d_in[9];
    float* out = (float*)d_out;

    float* xp = nullptr;
    float* hs = nullptr;
    cudaGetSymbolAddress((void**)&xp, g_xp);
    cudaGetSymbolAddress((void**)&hs, g_hs);

    const int MT = B_ * T_;   // 16384

    // Phase 0: Xp = x @ Wx + (bx + bh).   M=16384, N=1024, K=512
    {
        dim3 grid(H_ / 128, MT / 128);
        sgemm_bias_kernel<<<grid, 256>>>(x, Wx, bx, bh, xp, MT, H_, IN_);
    }

    // Phase 1: sequential scan (persistent kernel, grid barrier per step).
    // Writes all hidden states into g_hs and next_h into the output tail.
    {
        float* next_h = out + (size_t)2 * MT * OUT_;
        rnn_scan_kernel<<<128, 128>>>(h, Wh, next_h);
    }

    // Phase 2: td0 = hs @ W1 + b1 ; td1 = hs @ W2 + b2.  M=16384, N=512, K=1024
    {
        dim3 grid(OUT_ / 128, MT / 128);
        sgemm_bias_kernel<<<grid, 256>>>(hs, W1, b1, nullptr, out, MT, OUT_, H_);
        sgemm_bias_kernel<<<grid, 256>>>(hs, W2, b2, nullptr,
                                         out + (size_t)MT * OUT_, MT, OUT_, H_);
    }
}

// round 3
// speedup vs baseline: 1.2301x; 1.2301x over previous
#include <cuda_runtime.h>

// Problem dims (fixed by the dataset)
#define B_   32
#define T_   512
#define IN_  512
#define H_   1024
#define OUT_ 512

// ---------------------------------------------------------------------------
// Device scratch (allocation-free rule: __device__ globals)
// ---------------------------------------------------------------------------
__device__ float g_xp[(size_t)B_ * T_ * H_];   // x@Wx + bx + bh, [B][T][H]
__device__ float g_hs[(size_t)B_ * T_ * H_];   // hidden states   [B][T][H]
__device__ unsigned g_bar = 0;                 // grid barrier counter

// ---------------------------------------------------------------------------
// f32x2 packed math helpers
// ---------------------------------------------------------------------------
__device__ __forceinline__ unsigned long long ffma2(unsigned long long a,
                                                    unsigned long long b,
                                                    unsigned long long c) {
    unsigned long long d;
    asm("fma.rn.f32x2 %0, %1, %2, %3;" : "=l"(d) : "l"(a), "l"(b), "l"(c));
    return d;
}
__device__ __forceinline__ unsigned long long add2(unsigned long long a,
                                                   unsigned long long b) {
    unsigned long long d;
    asm("add.rn.f32x2 %0, %1, %2;" : "=l"(d) : "l"(a), "l"(b));
    return d;
}
__device__ __forceinline__ unsigned long long splat2(float x) {
    unsigned long long d;
    asm("mov.b64 %0, {%1, %2};" : "=l"(d) : "f"(x), "f"(x));
    return d;
}
__device__ __forceinline__ float2 unpack2(unsigned long long d) {
    float2 r;
    asm("mov.b64 {%0, %1}, %2;" : "=f"(r.x), "=f"(r.y) : "l"(d));
    return r;
}

// ---------------------------------------------------------------------------
// SGEMM with bias epilogue (unchanged from R1): C = A @ Bm + b1 (+ b2)
// 128x128 tile, BK=16, 256 threads, 8x8 per-thread tile via f32x2.
// Also resets the grid-barrier counter (runs before the scan kernel).
// ---------------------------------------------------------------------------
__global__ __launch_bounds__(256, 2) void sgemm_bias_kernel(
    const float* __restrict__ A, const float* __restrict__ Bm,
    const float* __restrict__ b1p, const float* __restrict__ b2p,
    float* __restrict__ C, int M, int N, int K)
{
    if (blockIdx.x == 0 && blockIdx.y == 0 && threadIdx.x == 0) g_bar = 0u;

    __shared__ __align__(16) float As[16][128];   // transposed: As[k][m]
    __shared__ __align__(16) float Bs[16][128];   // Bs[k][n]

    const int tid  = threadIdx.x;
    const int row0 = blockIdx.y * 128;
    const int col0 = blockIdx.x * 128;
    const int tx   = tid & 15;
    const int ty   = tid >> 4;

    const int aRow = tid >> 2;
    const int aK4  = (tid & 3) * 4;
    const int bRow = tid >> 5;
    const int bCol = (tid & 31) * 4;

    unsigned long long acc[8][4];
#pragma unroll
    for (int i = 0; i < 8; i++)
#pragma unroll
        for (int j = 0; j < 4; j++) acc[i][j] = 0ull;

    for (int k0 = 0; k0 < K; k0 += 16) {
        float4 av0 = *(const float4*)(A + (size_t)(row0 + aRow)      * K + k0 + aK4);
        float4 av1 = *(const float4*)(A + (size_t)(row0 + aRow + 64) * K + k0 + aK4);
        float4 bv0 = *(const float4*)(Bm + (size_t)(k0 + bRow)     * N + col0 + bCol);
        float4 bv1 = *(const float4*)(Bm + (size_t)(k0 + bRow + 8) * N + col0 + bCol);

        __syncthreads();
        As[aK4 + 0][aRow] = av0.x;  As[aK4 + 1][aRow] = av0.y;
        As[aK4 + 2][aRow] = av0.z;  As[aK4 + 3][aRow] = av0.w;
        As[aK4 + 0][aRow + 64] = av1.x;  As[aK4 + 1][aRow + 64] = av1.y;
        As[aK4 + 2][aRow + 64] = av1.z;  As[aK4 + 3][aRow + 64] = av1.w;
        *(float4*)&Bs[bRow][bCol]     = bv0;
        *(float4*)&Bs[bRow + 8][bCol] = bv1;
        __syncthreads();

#pragma unroll
        for (int kk = 0; kk < 16; kk++) {
            float4 a0 = *(const float4*)&As[kk][ty * 8];
            float4 a1 = *(const float4*)&As[kk][ty * 8 + 4];
            const unsigned long long* bp =
                (const unsigned long long*)&Bs[kk][tx * 8];
            unsigned long long bq0 = bp[0], bq1 = bp[1], bq2 = bp[2], bq3 = bp[3];
            float av[8] = {a0.x, a0.y, a0.z, a0.w, a1.x, a1.y, a1.z, a1.w};
#pragma unroll
            for (int i = 0; i < 8; i++) {
                unsigned long long a2 = splat2(av[i]);
                acc[i][0] = ffma2(a2, bq0, acc[i][0]);
                acc[i][1] = ffma2(a2, bq1, acc[i][1]);
                acc[i][2] = ffma2(a2, bq2, acc[i][2]);
                acc[i][3] = ffma2(a2, bq3, acc[i][3]);
            }
        }
    }

    const int crow = row0 + ty * 8;
    const int ccol = col0 + tx * 8;
    float bsum[8];
#pragma unroll
    for (int j = 0; j < 8; j++) {
        float bv = b1p[ccol + j];
        if (b2p) bv += b2p[ccol + j];
        bsum[j] = bv;
    }
#pragma unroll
    for (int i = 0; i < 8; i++) {
        float o[8];
#pragma unroll
        for (int j4 = 0; j4 < 4; j4++) {
            float2 v = unpack2(acc[i][j4]);
            o[2 * j4]     = v.x + bsum[2 * j4];
            o[2 * j4 + 1] = v.y + bsum[2 * j4 + 1];
        }
        float4* cp = (float4*)(C + (size_t)(crow + i) * N + ccol);
        cp[0] = make_float4(o[0], o[1], o[2], o[3]);
        cp[1] = make_float4(o[4], o[5], o[6], o[7]);
    }
}

// ---------------------------------------------------------------------------
// Persistent RNN scan kernel, v2.
//
// grid = 128 blocks (co-resident), block = 256 threads.
// Block owns j-columns [bx*8, bx*8+8); Wh slab (1024x8 = 32KB) resident in
// smem for the whole scan.
// Thread map: warp = ks (k-split, 8 splits of 128 k), lane = b (0..31).
//   -> weight LDS is a warp broadcast (all lanes share k)
//   -> 2 warps/SMSP hide L2 latency
// Each thread computes partials for all 4 j-pairs over its 128-k range with
// software-pipelined (distance-2) h loads, then a cross-ks smem reduction
// adds xp, applies tanh, stores, and the grid barrier advances the step.
// ---------------------------------------------------------------------------
__global__ __launch_bounds__(256, 1) void rnn_scan_kernel(
    const float* __restrict__ h0,   // [B][H]
    const float* __restrict__ Wh,   // [H][H]
    float* __restrict__ next_h)     // [B][H]
{
    __shared__ __align__(16) float whs[H_ * 8];                  // [k][jl] 32KB
    __shared__ __align__(16) unsigned long long red[8][32][4];   // 8KB

    const int tid   = threadIdx.x;
    const int ks    = tid >> 5;       // warp id = k-split
    const int b     = tid & 31;       // lane = batch row
    const int jbase = blockIdx.x * 8;
    const int k0    = ks * 128;

    // Load this block's Wh slab once (step-invariant).
    for (int idx = tid; idx < H_ * 8; idx += 256) {
        int k = idx >> 3, j = idx & 7;
        whs[idx] = Wh[(size_t)k * H_ + jbase + j];
    }
    __syncthreads();

    const int brow   = b * (T_ * H_);
    unsigned  target = gridDim.x;

    for (int t = 0; t < T_; t++) {
        const float* hp = ((t == 0) ? (h0 + b * H_)
                                    : (g_hs + brow + (t - 1) * H_)) + k0;

        unsigned long long a0 = 0ull, a1 = 0ull, a2 = 0ull, a3 = 0ull;

        // distance-2 software pipeline over 8 chunks of 16 k
        float4 hb[3][4];
#pragma unroll
        for (int q = 0; q < 4; q++) hb[0][q] = *(const float4*)(hp + q * 4);
#pragma unroll
        for (int q = 0; q < 4; q++) hb[1][q] = *(const float4*)(hp + 16 + q * 4);

#pragma unroll
        for (int c = 0; c < 8; c++) {
            if (c < 6) {
#pragma unroll
                for (int q = 0; q < 4; q++)
                    hb[(c + 2) % 3][q] = *(const float4*)(hp + (c + 2) * 16 + q * 4);
            }
            const float* hv = (const float*)hb[c % 3];
            const float* wbase = whs + ((k0 + c * 16) << 3);
#pragma unroll
            for (int i = 0; i < 16; i++) {
                const ulonglong2* wk = (const ulonglong2*)(wbase + (i << 3));
                ulonglong2 w01 = wk[0];
                ulonglong2 w23 = wk[1];
                unsigned long long s = splat2(hv[i]);
                a0 = ffma2(s, w01.x, a0);
                a1 = ffma2(s, w01.y, a1);
                a2 = ffma2(s, w23.x, a2);
                a3 = ffma2(s, w23.y, a3);
            }
        }

        // cross-ks reduction via smem
        red[ks][b][0] = a0;  red[ks][b][1] = a1;
        red[ks][b][2] = a2;  red[ks][b][3] = a3;
        __syncthreads();

        if (tid < 128) {
            const int rb = tid >> 2;      // batch row 0..31
            const int jp = tid & 3;       // j-pair 0..3
            const int rrow = rb * (T_ * H_);
            // issue xp load early to hide its L2 latency under the LDS chain
            unsigned long long xpv =
                *(const unsigned long long*)(g_xp + rrow + t * H_ + jbase + 2 * jp);

            unsigned long long s01 = add2(red[0][rb][jp], red[1][rb][jp]);
            unsigned long long s23 = add2(red[2][rb][jp], red[3][rb][jp]);
            unsigned long long s45 = add2(red[4][rb][jp], red[5][rb][jp]);
            unsigned long long s67 = add2(red[6][rb][jp], red[7][rb][jp]);
            unsigned long long s = add2(add2(s01, s23), add2(s45, s67));
            s = add2(s, xpv);

            float2 v = unpack2(s);
            v.x = tanhf(v.x);
            v.y = tanhf(v.y);
            *(float2*)(g_hs + rrow + t * H_ + jbase + 2 * jp) = v;
            if (t == T_ - 1)
                *(float2*)(next_h + rb * H_ + jbase + 2 * jp) = v;
        }

        // ---- grid barrier ----
        __threadfence();
        __syncthreads();
        if (tid == 0) {
            unsigned arrived = atomicAdd(&g_bar, 1u) + 1u;
            if (arrived < target) {
                while (*(volatile unsigned*)&g_bar < target) { }
            }
        }
        __syncthreads();
        target += gridDim.x;
    }
}

// ---------------------------------------------------------------------------
// kernel_launch: 4 launches, graph-capturable, default stream.
// Inputs: 0:x 1:h 2:Wx 3:bx 4:Wh 5:bh 6:W1 7:b1 8:W2 9:b2
// Output: [td0 (B*T*OUT) | td1 (B*T*OUT) | next_h (B*H)]
// ---------------------------------------------------------------------------
extern "C" void kernel_launch(void* const* d_in, const int* in_sizes, int n_in,
                              void* d_out, int out_size)
{
    (void)in_sizes; (void)n_in; (void)out_size;
    const float* x  = (const float*)d_in[0];
    const float* h  = (const float*)d_in[1];
    const float* Wx = (const float*)d_in[2];
    const float* bx = (const float*)d_in[3];
    const float* Wh = (const float*)d_in[4];
    const float* bh = (const float*)d_in[5];
    const float* W1 = (const float*)d_in[6];
    const float* b1 = (const float*)d_in[7];
    const float* W2 = (const float*)d_in[8];
    const float* b2 = (const float*)d_in[9];
    float* out = (float*)d_out;

    float* xp = nullptr;
    float* hs = nullptr;
    cudaGetSymbolAddress((void**)&xp, g_xp);
    cudaGetSymbolAddress((void**)&hs, g_hs);

    const int MT = B_ * T_;   // 16384

    // Phase 0: Xp = x @ Wx + (bx + bh).   M=16384, N=1024, K=512
    {
        dim3 grid(H_ / 128, MT / 128);
        sgemm_bias_kernel<<<grid, 256>>>(x, Wx, bx, bh, xp, MT, H_, IN_);
    }

    // Phase 1: sequential scan (persistent kernel, grid barrier per step).
    {
        float* next_h = out + (size_t)2 * MT * OUT_;
        rnn_scan_kernel<<<128, 256>>>(h, Wh, next_h);
    }

    // Phase 2: td0 = hs @ W1 + b1 ; td1 = hs @ W2 + b2.  M=16384, N=512, K=1024
    {
        dim3 grid(OUT_ / 128, MT / 128);
        sgemm_bias_kernel<<<grid, 256>>>(hs, W1, b1, nullptr, out, MT, OUT_, H_);
        sgemm_bias_kernel<<<grid, 256>>>(hs, W2, b2, nullptr,
                                         out + (size_t)MT * OUT_, MT, OUT_, H_);
    }
}